// round 15
// baseline (speedup 1.0000x reference)
#include <cuda_runtime.h>
#include <cstdint>

// Fixed problem shape
#define NB 8
#define HW (640*640)        // 409600
#define NL 33
#define NREP 32             // accumulator replicas (same-address chain spreading)
#define TPB 256
#define PPT 8               // both phases: 8 px/thread
#define PIX_PER_BLOCK (TPB*PPT)              // 2048
#define BPB (HW/PIX_PER_BLOCK)               // 200 exact
#define GRID1 (NB*BPB)                       // 1600 phase1 blocks
#define GRID2 (NB*BPB)                       // 1600 phase2 blocks
#define GRID_ALL (GRID1+GRID2)               // phase1 bids < phase2 bids
#define FULLM 0xFFFFFFFFu

// 256B-aligned: consecutive hot accumulators differ in addr bits >=8 -> spread
// across L2 slices (bit 7 transparent in the slice hash).
struct alignas(256) Accum {
    float4   sums;     // kernel-masked embedding sums
    unsigned cnt;      // (cnt_i << 16) | cnt_k
    float    pad[59];
};

// Per-batch means, padded/aligned so no 128B line crosses batches.
struct alignas(128) MeanBlk {
    float4 m[NL];
    float  w[NL];
    float  pad[27];    // -> 768 B
};

// Zero-initialized at load; epilogue resets tickets/flags; phase2 blocks reset
// their batch's g_acc slice -> graph replays are self-consistent.
__device__ Accum    g_acc[NREP][NB][NL];   // 2.1 MB
__device__ MeanBlk  g_mb[NB];
__device__ unsigned g_lab[NB * HW / 4];    // packed per-pixel labels (4 x u8)
__device__ volatile unsigned g_ready[NB];  // per-batch means-published flag
__device__ unsigned g_done1[NB];           // per-batch phase1 ticket
__device__ unsigned g_done2;               // global phase2 ticket
__device__ float    g_scalar;

__device__ __forceinline__ void red_add_v4f(float4* p, float a, float b, float c, float d) {
    asm volatile("red.global.add.v4.f32 [%0], {%1, %2, %3, %4};"
                 :: "l"(p), "f"(a), "f"(b), "f"(c), "f"(d) : "memory");
}
__device__ __forceinline__ void red_add_u32(unsigned* p, unsigned v) {
    asm volatile("red.global.add.u32 [%0], %1;" :: "l"(p), "r"(v) : "memory");
}
__device__ __forceinline__ void red_add_f32(float* p, float v) {
    asm volatile("red.global.add.f32 [%0], %1;" :: "l"(p), "f"(v) : "memory");
}
__device__ __forceinline__ float sqrt_approx(float x) {
    float r; asm("sqrt.approx.f32 %0, %1;" : "=f"(r) : "f"(x)); return r;
}

// ---------------- phase 1 body: one 2048-px tile of batch b ------------------
__device__ __forceinline__ void phase1_body(
    int blk, const float* __restrict__ emb, const int* __restrict__ inst,
    const float* __restrict__ kern, const float* __restrict__ tmk) {
    __shared__ unsigned scnt[NL];
    __shared__ float4   psum[NL][4];
    __shared__ unsigned pcnt[NL][4];
    __shared__ int slast;

    int b   = blk / BPB;
    int tid = threadIdx.x;
    unsigned lane = tid & 31u;
    int wid = tid >> 5;
    unsigned rep = (unsigned)(blk * (TPB / 32) + wid) & (NREP - 1);

    if (tid < NL) scnt[tid] = 0u;

    int p    = (blk - b * BPB) * PIX_PER_BLOCK + tid * PPT;
    int base = b * HW + p;

    // 6 independent front-batched mask loads (MLP=6).
    int4   iv0 = *reinterpret_cast<const int4*>(inst + base);
    int4   iv1 = *reinterpret_cast<const int4*>(inst + base + 4);
    float4 tv0 = *reinterpret_cast<const float4*>(tmk + base);
    float4 tv1 = *reinterpret_cast<const float4*>(tmk + base + 4);
    float4 kv0 = *reinterpret_cast<const float4*>(kern + base);
    float4 kv1 = *reinterpret_cast<const float4*>(kern + base + 4);

    int li[PPT]; bool kk[PPT];
    {
        const int*   ivp0 = reinterpret_cast<const int*>(&iv0);
        const int*   ivp1 = reinterpret_cast<const int*>(&iv1);
        const float* tvp0 = reinterpret_cast<const float*>(&tv0);
        const float* tvp1 = reinterpret_cast<const float*>(&tv1);
        const float* kvp0 = reinterpret_cast<const float*>(&kv0);
        const float* kvp1 = reinterpret_cast<const float*>(&kv1);
#pragma unroll
        for (int j = 0; j < 4; j++) {
            int l0 = (tvp0[j] > 0.5f) ? ivp0[j] : 0;
            if ((unsigned)l0 >= NL) l0 = 0;
            li[j] = l0;  kk[j] = (kvp0[j] > 0.5f) && (l0 != 0);
            int l1 = (tvp1[j] > 0.5f) ? ivp1[j] : 0;
            if ((unsigned)l1 >= NL) l1 = 0;
            li[4 + j] = l1;  kk[4 + j] = (kvp1[j] > 0.5f) && (l1 != 0);
        }
    }

    // Labels for phase 2 (8 px -> uint2, 8B aligned).
    {
        uint2 lw;
        lw.x = (unsigned)li[0] | ((unsigned)li[1] << 8)
             | ((unsigned)li[2] << 16) | ((unsigned)li[3] << 24);
        lw.y = (unsigned)li[4] | ((unsigned)li[5] << 8)
             | ((unsigned)li[6] << 16) | ((unsigned)li[7] << 24);
        *reinterpret_cast<uint2*>(&g_lab[base >> 2]) = lw;
    }

    __syncthreads();   // scnt zeroed

    // Two 4-px halves: emb loads conditional per half (~33% of halves skip).
#pragma unroll
    for (int h = 0; h < 2; h++) {
        int  o  = 4 * h;
        bool anyk = kk[o] | kk[o + 1] | kk[o + 2] | kk[o + 3];
        float4 e0 = make_float4(0.f,0.f,0.f,0.f), e1 = e0, e2 = e0, e3 = e0;
        if (anyk) {
            const float* eb = emb + (size_t)b * 4 * HW + p + o;
            e0 = *reinterpret_cast<const float4*>(eb);
            e1 = *reinterpret_cast<const float4*>(eb + HW);
            e2 = *reinterpret_cast<const float4*>(eb + 2 * HW);
            e3 = *reinterpret_cast<const float4*>(eb + 3 * HW);
        }
        const float* c0 = reinterpret_cast<const float*>(&e0);
        const float* c1 = reinterpret_cast<const float*>(&e1);
        const float* c2 = reinterpret_cast<const float*>(&e2);
        const float* c3 = reinterpret_cast<const float*>(&e3);
#pragma unroll
        for (int j = 0; j < 4; j++) {
            int jj = o + j;
            unsigned mm = __match_any_sync(FULLM, li[jj]);
            unsigned kb = __ballot_sync(FULLM, kk[jj]);
            if (li[jj] != 0 && (unsigned)(__ffs(mm) - 1) == lane)
                atomicAdd(&scnt[li[jj]], ((unsigned)__popc(mm) << 16)
                                         | (unsigned)__popc(mm & kb));
            if (kk[jj])
                red_add_v4f(&g_acc[rep][b][li[jj]].sums, c0[j], c1[j], c2[j], c3[j]);
        }
    }

    __syncthreads();
    if (tid >= 1 && tid < NL) {
        unsigned v = scnt[tid];
        if (v) red_add_u32(&g_acc[(unsigned)(blk + tid) & (NREP - 1)][b][tid].cnt, v);
    }

    // ---- per-batch ticket: last block of batch b computes means(b) ----------
    __threadfence();
    __syncthreads();
    if (tid == 0)
        slast = (atomicAdd(&g_done1[b], 1u) == (unsigned)(BPB - 1)) ? 1 : 0;
    __syncthreads();
    if (!slast) return;
    __threadfence();   // acquire all batch-b REDs

    // Parallelized gather: 132 threads x 8 reps -> 4 partials per label.
    if (tid < NL * 4) {
        int l = tid >> 2, sub = tid & 3;
        float sx = 0.f, sy = 0.f, sz = 0.f, sww = 0.f;
        unsigned c = 0u;
#pragma unroll
        for (int r = 0; r < 8; r++) {
            const Accum& a = g_acc[sub * 8 + r][b][l];
            sx += a.sums.x; sy += a.sums.y; sz += a.sums.z; sww += a.sums.w;
            c += a.cnt;
        }
        psum[l][sub] = make_float4(sx, sy, sz, sww);
        pcnt[l][sub] = c;
    }
    __syncthreads();
    if (tid < NL) {
        float sx = 0.f, sy = 0.f, sz = 0.f, sww = 0.f;
        unsigned c = 0u;
#pragma unroll
        for (int s = 0; s < 4; s++) {
            float4 v = psum[tid][s];
            sx += v.x; sy += v.y; sz += v.z; sww += v.w;
            c += pcnt[tid][s];
        }
        float cnt_k = (float)(c & 0xFFFFu);
        float cnt_i = (float)(c >> 16);
        float inv = (tid == 0) ? 0.f : (1.f / fmaxf(cnt_k, 1.f));
        g_mb[b].m[tid] = make_float4(sx * inv, sy * inv, sz * inv, sww * inv);
        g_mb[b].w[tid] = (tid == 0) ? 0.f : (1.f / (32.f * fmaxf(cnt_i, 1.f)));
    }
    __threadfence();   // publish means before flag
    __syncthreads();
    if (tid == 0) atomicExch((unsigned*)&g_ready[b], 1u);
}

// ---------------- phase 2 body: loss tile (8 px/thread) + epilogue -----------
__device__ __forceinline__ void phase2_body(
    int blk, const float* __restrict__ emb, float* __restrict__ out) {
    __shared__ float4 smean[NL];
    __shared__ float  swt[NL];
    __shared__ float  swred[8];
    __shared__ int    slast;

    int b   = blk / BPB;
    int tid = threadIdx.x;

    // Wait for means(b). All phase1 bids precede phase2 bids -> progress safe.
    if (tid == 0) {
        while (g_ready[b] == 0u) __nanosleep(64);
    }
    __syncthreads();
    __threadfence();   // acquire means

    if (tid < NL) { smean[tid] = g_mb[b].m[tid]; swt[tid] = g_mb[b].w[tid]; }

    // Distributed reset of batch b's accumulator slice (6 structs x 200 blocks
    // covers NREP*NL = 1056). Means(b) already consumed.
    {
        int r0 = (blk - b * BPB) * 6;
#pragma unroll
        for (int k = 0; k < 6; k++) {
            int s = r0 + k;
            if (s < NREP * NL) {
                Accum* a = &g_acc[s / NL][b][s % NL];
                a->sums = make_float4(0.f, 0.f, 0.f, 0.f);
                a->cnt  = 0u;
            }
        }
    }
    __syncthreads();

    int p    = (blk - b * BPB) * PIX_PER_BLOCK + tid * PPT;
    int base = b * HW + p;

    // Front-batched MLP=9: uint2 labels + 8 x float4 emb.
    uint2 lab2 = *reinterpret_cast<const uint2*>(&g_lab[base >> 2]);
    const float* eb = emb + (size_t)b * 4 * HW + p;
    float4 e[4][2];
#pragma unroll
    for (int c = 0; c < 4; c++) {
        e[c][0] = *reinterpret_cast<const float4*>(eb + c * HW);
        e[c][1] = *reinterpret_cast<const float4*>(eb + c * HW + 4);
    }

    float acc = 0.f;   // branchless: w[0]=0 kills unmasked pixels
#pragma unroll
    for (int h = 0; h < 2; h++) {
        unsigned lab = (h == 0) ? lab2.x : lab2.y;
        const float* c0 = reinterpret_cast<const float*>(&e[0][h]);
        const float* c1 = reinterpret_cast<const float*>(&e[1][h]);
        const float* c2 = reinterpret_cast<const float*>(&e[2][h]);
        const float* c3 = reinterpret_cast<const float*>(&e[3][h]);
#pragma unroll
        for (int j = 0; j < 4; j++) {
            int li = (int)((lab >> (8 * j)) & 0xFFu);
            float4 m = smean[li];
            float wv = swt[li];
            float dx = c0[j] - m.x, dy = c1[j] - m.y;
            float dz = c2[j] - m.z, dw = c3[j] - m.w;
            float s  = dx*dx + dy*dy + dz*dz + dw*dw;
            float tt = fmaxf(sqrt_approx(s) - 0.5f, 0.f);   // DELTA_V = 0.5
            acc = fmaf(wv, __logf(fmaf(tt, tt, 1.f)), acc);
        }
    }

#pragma unroll
    for (int off = 16; off; off >>= 1)
        acc += __shfl_down_sync(FULLM, acc, off);
    if ((tid & 31) == 0) swred[tid >> 5] = acc;
    __syncthreads();
    if (tid == 0) {
        float s2 = 0.f;
#pragma unroll
        for (int w = 0; w < 8; w++) s2 += swred[w];
        red_add_f32(&g_scalar, s2);
        __threadfence();
        slast = (atomicAdd(&g_done2, 1u) == (unsigned)(GRID2 - 1)) ? 1 : 0;
    }
    __syncthreads();
    if (!slast) return;

    // ---------- epilogue: l_dis + l_reg, write out, reset tickets ------------
    __threadfence();
    __shared__ float sred2[TPB];
    float a2 = 0.f;
    for (int i = tid; i < NB * 32; i += TPB) {            // l_reg
        int bb = i >> 5, l = (i & 31) + 1;
        float4 m = g_mb[bb].m[l];
        float n = sqrtf(m.x*m.x + m.y*m.y + m.z*m.z + m.w*m.w);
        a2 += logf(n + 1.f) * (0.001f / 33.0f);
    }
    for (int idx = tid; idx < NB * 32 * 32; idx += TPB) { // l_dis, i != j
        int bb = idx >> 10, rr = idx & 1023, i = rr >> 5, j = rr & 31;
        if (i != j) {
            float4 mi = g_mb[bb].m[i + 1], mj = g_mb[bb].m[j + 1];
            float dx = mi.x - mj.x, dy = mi.y - mj.y;
            float dz = mi.z - mj.z, dw = mi.w - mj.w;
            float pd = sqrtf(dx*dx + dy*dy + dz*dz + dw*dw);
            float tt = fmaxf(3.0f - pd, 0.f);             // 2*DELTA_D
            a2 += logf(fmaf(tt, tt, 1.f)) * (1.0f / 992.0f);
        }
    }
    sred2[tid] = a2;
    __syncthreads();
    for (int s = TPB / 2; s > 0; s >>= 1) {
        if (tid < s) sred2[tid] += sred2[tid + s];
        __syncthreads();
    }
    if (tid == 0) {
        float S = *(volatile float*)&g_scalar;   // l_agg (weights folded in)
        out[0] = (S + sred2[0]) * (1.0f / NB);   // LOSS_WEIGHT = 1
        g_done2 = 0u;
        g_scalar = 0.f;
    }
    if (tid < NB) { g_done1[tid] = 0u; *(unsigned*)&g_ready[tid] = 0u; }
}

// ---------------- single fused launch ----------------------------------------
__global__ __launch_bounds__(TPB) void k_all(
    const float* __restrict__ emb, const int* __restrict__ inst,
    const float* __restrict__ kern, const float* __restrict__ tmk,
    float* __restrict__ out) {
    int bid = (int)blockIdx.x;
    if (bid < GRID1)
        phase1_body(bid, emb, inst, kern, tmk);
    else
        phase2_body(bid - GRID1, emb, out);
}

extern "C" void kernel_launch(void* const* d_in, const int* in_sizes, int n_in,
                              void* d_out, int out_size) {
    (void)in_sizes; (void)n_in; (void)out_size;
    const float* emb  = (const float*)d_in[0];
    const int*   inst = (const int*)d_in[1];
    const float* kern = (const float*)d_in[2];
    const float* tmk  = (const float*)d_in[3];
    float* out = (float*)d_out;

    k_all<<<GRID_ALL, TPB>>>(emb, inst, kern, tmk, out);
}

// round 16
// speedup vs baseline: 1.0494x; 1.0494x over previous
#include <cuda_runtime.h>
#include <cstdint>

// Fixed problem shape
#define NB 8
#define HW (640*640)        // 409600
#define NL 33
#define NREP 32             // accumulator replicas (same-address chain spreading)
#define TPB 256
#define PPT 4
#define PIX_PER_BLOCK (TPB*PPT)              // 1024
#define BLOCKS_PER_BATCH (HW/PIX_PER_BLOCK)  // 400 exact
#define GRID_MAIN (NB*BLOCKS_PER_BATCH)      // 3200 per phase
#define GRID_ALL (2*GRID_MAIN)               // 6400: phase1 bids < phase2 bids
#define FULLM 0xFFFFFFFFu

// 256B-aligned: consecutive hot accumulators differ in addr bits >=8 -> spread
// across L2 slices (bit 7 transparent in the slice hash).
struct alignas(256) Accum {
    float4   sums;     // kernel-masked embedding sums
    unsigned cnt;      // (cnt_i << 16) | cnt_k
    float    pad[59];
};

// Per-batch means, padded/aligned so no 128B line crosses batches.
struct alignas(128) MeanBlk {
    float4 m[NL];
    float  w[NL];
    float  pad[27];    // -> 768 B
};

// Zero-initialized at load; epilogue resets tickets/flags; phase2 blocks reset
// their batch's g_acc slice -> graph replays are self-consistent.
__device__ Accum    g_acc[NREP][NB][NL];   // 2.1 MB
__device__ MeanBlk  g_mb[NB];
__device__ unsigned g_lab[NB * HW / 4];    // packed per-pixel labels (4 x u8)
__device__ volatile unsigned g_ready[NB];  // per-batch means-published flag
__device__ unsigned g_done1[NB];           // per-batch phase1 ticket
__device__ unsigned g_done2;               // global phase2 ticket
__device__ float    g_scalar;

__device__ __forceinline__ void red_add_v4f(float4* p, float a, float b, float c, float d) {
    asm volatile("red.global.add.v4.f32 [%0], {%1, %2, %3, %4};"
                 :: "l"(p), "f"(a), "f"(b), "f"(c), "f"(d) : "memory");
}
__device__ __forceinline__ void red_add_u32(unsigned* p, unsigned v) {
    asm volatile("red.global.add.u32 [%0], %1;" :: "l"(p), "r"(v) : "memory");
}
__device__ __forceinline__ void red_add_f32(float* p, float v) {
    asm volatile("red.global.add.f32 [%0], %1;" :: "l"(p), "f"(v) : "memory");
}
__device__ __forceinline__ float sqrt_approx(float x) {
    float r; asm("sqrt.approx.f32 %0, %1;" : "=f"(r) : "f"(x)); return r;
}

// ---------------- phase 1 body: one 1024-px tile of batch b ------------------
__device__ __forceinline__ void phase1_body(
    int blk, const float* __restrict__ emb, const int* __restrict__ inst,
    const float* __restrict__ kern, const float* __restrict__ tmk) {
    __shared__ unsigned scnt[NL];
    __shared__ float4   psum[NL][4];
    __shared__ unsigned pcnt[NL][4];
    __shared__ int slast;

    int b   = blk / BLOCKS_PER_BATCH;
    int tid = threadIdx.x;
    unsigned lane = tid & 31u;
    int wid = tid >> 5;
    unsigned rep = (unsigned)(blk * (TPB / 32) + wid) & (NREP - 1);

    if (tid < NL) scnt[tid] = 0u;

    int p    = (blk - b * BLOCKS_PER_BATCH) * PIX_PER_BLOCK + tid * PPT;
    int base = b * HW + p;

    int4   iv = *reinterpret_cast<const int4*>(inst + base);
    float4 tv = *reinterpret_cast<const float4*>(tmk + base);
    float4 kv = *reinterpret_cast<const float4*>(kern + base);
    const int*   ivp = reinterpret_cast<const int*>(&iv);
    const float* tvp = reinterpret_cast<const float*>(&tv);
    const float* kvp = reinterpret_cast<const float*>(&kv);

    int  li[PPT]; bool kk[PPT]; bool anyk = false;
#pragma unroll
    for (int j = 0; j < PPT; j++) {
        int l = (tvp[j] > 0.5f) ? ivp[j] : 0;
        if ((unsigned)l >= NL) l = 0;
        li[j] = l;
        kk[j] = (kvp[j] > 0.5f) && (l != 0);
        anyk |= kk[j];
    }

    // Labels for phase 2.
    g_lab[base >> 2] = (unsigned)li[0] | ((unsigned)li[1] << 8)
                     | ((unsigned)li[2] << 16) | ((unsigned)li[3] << 24);

    // emb only feeds kernel-masked sums: skip loads when no pixel qualifies.
    float4 e0 = make_float4(0.f,0.f,0.f,0.f), e1 = e0, e2 = e0, e3 = e0;
    if (anyk) {
        const float* eb = emb + (size_t)b * 4 * HW + p;
        e0 = *reinterpret_cast<const float4*>(eb);
        e1 = *reinterpret_cast<const float4*>(eb + HW);
        e2 = *reinterpret_cast<const float4*>(eb + 2 * HW);
        e3 = *reinterpret_cast<const float4*>(eb + 3 * HW);
    }
    const float* c0 = reinterpret_cast<const float*>(&e0);
    const float* c1 = reinterpret_cast<const float*>(&e1);
    const float* c2 = reinterpret_cast<const float*>(&e2);
    const float* c3 = reinterpret_cast<const float*>(&e3);

    __syncthreads();   // scnt zeroed

#pragma unroll
    for (int j = 0; j < PPT; j++) {
        unsigned mm = __match_any_sync(FULLM, li[j]);   // warp-aggregate counts
        unsigned kb = __ballot_sync(FULLM, kk[j]);
        if (li[j] != 0 && (unsigned)(__ffs(mm) - 1) == lane)
            atomicAdd(&scnt[li[j]], ((unsigned)__popc(mm) << 16)
                                    | (unsigned)__popc(mm & kb));
        if (kk[j])
            red_add_v4f(&g_acc[rep][b][li[j]].sums, c0[j], c1[j], c2[j], c3[j]);
    }

    __syncthreads();
    if (tid >= 1 && tid < NL) {
        unsigned v = scnt[tid];
        if (v) red_add_u32(&g_acc[(unsigned)(blk + tid) & (NREP - 1)][b][tid].cnt, v);
    }

    // ---- per-batch ticket: last block of batch b computes means(b) ----------
    __threadfence();
    __syncthreads();
    if (tid == 0)
        slast = (atomicAdd(&g_done1[b], 1u) == (unsigned)(BLOCKS_PER_BATCH - 1)) ? 1 : 0;
    __syncthreads();
    if (!slast) return;
    __threadfence();   // acquire all batch-b REDs

    // Parallelized gather: 132 threads x 8 reps -> 4 partials per label
    // (short 8-deep load chain per thread instead of 32-deep).
    if (tid < NL * 4) {
        int l = tid >> 2, sub = tid & 3;
        float sx = 0.f, sy = 0.f, sz = 0.f, sww = 0.f;
        unsigned c = 0u;
#pragma unroll
        for (int r = 0; r < 8; r++) {
            const Accum& a = g_acc[sub * 8 + r][b][l];
            sx += a.sums.x; sy += a.sums.y; sz += a.sums.z; sww += a.sums.w;
            c += a.cnt;
        }
        psum[l][sub] = make_float4(sx, sy, sz, sww);
        pcnt[l][sub] = c;
    }
    __syncthreads();
    if (tid < NL) {
        float sx = 0.f, sy = 0.f, sz = 0.f, sww = 0.f;
        unsigned c = 0u;
#pragma unroll
        for (int s = 0; s < 4; s++) {
            float4 v = psum[tid][s];
            sx += v.x; sy += v.y; sz += v.z; sww += v.w;
            c += pcnt[tid][s];
        }
        float cnt_k = (float)(c & 0xFFFFu);
        float cnt_i = (float)(c >> 16);
        float inv = (tid == 0) ? 0.f : (1.f / fmaxf(cnt_k, 1.f));
        g_mb[b].m[tid] = make_float4(sx * inv, sy * inv, sz * inv, sww * inv);
        g_mb[b].w[tid] = (tid == 0) ? 0.f : (1.f / (32.f * fmaxf(cnt_i, 1.f)));
    }
    __threadfence();   // publish means before flag
    __syncthreads();
    if (tid == 0) atomicExch((unsigned*)&g_ready[b], 1u);
}

// ---------------- phase 2 body: loss tile + epilogue -------------------------
__device__ __forceinline__ void phase2_body(
    int blk, const float* __restrict__ emb, float* __restrict__ out) {
    __shared__ float4 smean[NL];
    __shared__ float  swt[NL];
    __shared__ float  swred[8];
    __shared__ int    slast;

    int b   = blk / BLOCKS_PER_BATCH;
    int tid = threadIdx.x;

    // Wait for means(b). Phase1 bids all precede phase2 bids -> progress safe.
    if (tid == 0) {
        while (g_ready[b] == 0u) __nanosleep(32);
    }
    __syncthreads();
    __threadfence();   // acquire means

    if (tid < NL) { smean[tid] = g_mb[b].m[tid]; swt[tid] = g_mb[b].w[tid]; }

    // Distributed reset of batch b's accumulator slice for the next replay
    // (3 structs x 400 blocks covers NREP*NL = 1056).
    {
        int r0 = (blk - b * BLOCKS_PER_BATCH) * 3;
#pragma unroll
        for (int k = 0; k < 3; k++) {
            int s = r0 + k;
            if (s < NREP * NL) {
                Accum* a = &g_acc[s / NL][b][s % NL];
                a->sums = make_float4(0.f, 0.f, 0.f, 0.f);
                a->cnt  = 0u;
            }
        }
    }
    __syncthreads();

    int p    = (blk - b * BLOCKS_PER_BATCH) * PIX_PER_BLOCK + tid * PPT;
    int base = b * HW + p;

    unsigned lab = g_lab[base >> 2];
    const float* eb = emb + (size_t)b * 4 * HW + p;
    float4 e0 = *reinterpret_cast<const float4*>(eb);
    float4 e1 = *reinterpret_cast<const float4*>(eb + HW);
    float4 e2 = *reinterpret_cast<const float4*>(eb + 2 * HW);
    float4 e3 = *reinterpret_cast<const float4*>(eb + 3 * HW);
    const float* c0 = reinterpret_cast<const float*>(&e0);
    const float* c1 = reinterpret_cast<const float*>(&e1);
    const float* c2 = reinterpret_cast<const float*>(&e2);
    const float* c3 = reinterpret_cast<const float*>(&e3);

    float acc = 0.f;   // branchless: w[0]=0 kills unmasked pixels
#pragma unroll
    for (int j = 0; j < PPT; j++) {
        int li = (int)((lab >> (8 * j)) & 0xFFu);
        float4 m = smean[li];
        float wv = swt[li];
        float dx = c0[j] - m.x, dy = c1[j] - m.y;
        float dz = c2[j] - m.z, dw = c3[j] - m.w;
        float s  = dx*dx + dy*dy + dz*dz + dw*dw;
        float tt = fmaxf(sqrt_approx(s) - 0.5f, 0.f);     // DELTA_V = 0.5
        acc = fmaf(wv, __logf(fmaf(tt, tt, 1.f)), acc);
    }

#pragma unroll
    for (int off = 16; off; off >>= 1)
        acc += __shfl_down_sync(FULLM, acc, off);
    if ((tid & 31) == 0) swred[tid >> 5] = acc;
    __syncthreads();
    if (tid == 0) {
        float s2 = 0.f;
#pragma unroll
        for (int w = 0; w < 8; w++) s2 += swred[w];
        red_add_f32(&g_scalar, s2);
        __threadfence();
        slast = (atomicAdd(&g_done2, 1u) == (unsigned)(GRID_MAIN - 1)) ? 1 : 0;
    }
    __syncthreads();
    if (!slast) return;

    // ---------- epilogue: l_dis + l_reg, write out, reset tickets ------------
    __threadfence();
    __shared__ float sred2[TPB];
    float a2 = 0.f;
    for (int i = tid; i < NB * 32; i += TPB) {            // l_reg
        int bb = i >> 5, l = (i & 31) + 1;
        float4 m = g_mb[bb].m[l];
        float n = sqrtf(m.x*m.x + m.y*m.y + m.z*m.z + m.w*m.w);
        a2 += logf(n + 1.f) * (0.001f / 33.0f);
    }
    for (int idx = tid; idx < NB * 32 * 32; idx += TPB) { // l_dis, i != j
        int bb = idx >> 10, rr = idx & 1023, i = rr >> 5, j = rr & 31;
        if (i != j) {
            float4 mi = g_mb[bb].m[i + 1], mj = g_mb[bb].m[j + 1];
            float dx = mi.x - mj.x, dy = mi.y - mj.y;
            float dz = mi.z - mj.z, dw = mi.w - mj.w;
            float pd = sqrtf(dx*dx + dy*dy + dz*dz + dw*dw);
            float tt = fmaxf(3.0f - pd, 0.f);             // 2*DELTA_D
            a2 += logf(fmaf(tt, tt, 1.f)) * (1.0f / 992.0f);
        }
    }
    sred2[tid] = a2;
    __syncthreads();
    for (int s = TPB / 2; s > 0; s >>= 1) {
        if (tid < s) sred2[tid] += sred2[tid + s];
        __syncthreads();
    }
    if (tid == 0) {
        float S = *(volatile float*)&g_scalar;   // l_agg (weights folded in)
        out[0] = (S + sred2[0]) * (1.0f / NB);   // LOSS_WEIGHT = 1
        g_done2 = 0u;
        g_scalar = 0.f;
    }
    if (tid < NB) { g_done1[tid] = 0u; *(unsigned*)&g_ready[tid] = 0u; }
}

// ---------------- single fused launch ----------------------------------------
__global__ __launch_bounds__(TPB) void k_all(
    const float* __restrict__ emb, const int* __restrict__ inst,
    const float* __restrict__ kern, const float* __restrict__ tmk,
    float* __restrict__ out) {
    int bid = (int)blockIdx.x;
    if (bid < GRID_MAIN)
        phase1_body(bid, emb, inst, kern, tmk);
    else
        phase2_body(bid - GRID_MAIN, emb, out);
}

extern "C" void kernel_launch(void* const* d_in, const int* in_sizes, int n_in,
                              void* d_out, int out_size) {
    (void)in_sizes; (void)n_in; (void)out_size;
    const float* emb  = (const float*)d_in[0];
    const int*   inst = (const int*)d_in[1];
    const float* kern = (const float*)d_in[2];
    const float* tmk  = (const float*)d_in[3];
    float* out = (float*)d_out;

    k_all<<<GRID_ALL, TPB>>>(emb, inst, kern, tmk, out);
}